// round 15
// baseline (speedup 1.0000x reference)
#include <cuda_runtime.h>
#include <cuda_bf16.h>
#include <math.h>
#include <stdint.h>

#define HW   (128 * 128)
#define Hh   128
#define Ww   128
#define Bb   4
#define Cc   64
#define Oo   64

// Scratch: offsets/mask planes [B][27][H][W]  (0..8 dy_k, 9..17 dx_k, 18..26 mask_k)
__device__ float g_scratch[Bb * 27 * HW];

#define ROWW 36
// deform weight images (tap-major)
__device__ __align__(16) uint32_t g_wbh[9 * 64 * ROWW];
__device__ __align__(16) uint32_t g_wbl[9 * 64 * ROWW];
// offmask weight images
__device__ __align__(16) uint32_t g_wboh[9 * 24 * ROWW];
__device__ __align__(16) uint32_t g_wbol[9 * 24 * ROWW];
__device__ __align__(16) uint32_t g_wbmh[9 * 16 * ROWW];
__device__ __align__(16) uint32_t g_wbml[9 * 16 * ROWW];

// ---------------- helpers ----------------
__device__ __forceinline__ uint32_t bfpack(float a, float b) {
    __nv_bfloat162 t = __floats2bfloat162_rn(a, b);
    return *(uint32_t*)&t;
}
__device__ __forceinline__ void bfsplit(float s, float &hi, float &lo) {
    hi = __bfloat162float(__float2bfloat16(s));
    lo = s - hi;
}

#define MMA_BF16(d, a, b0, b1) \
    asm volatile("mma.sync.aligned.m16n8k16.row.col.f32.bf16.bf16.f32 " \
        "{%0,%1,%2,%3}, {%4,%5,%6,%7}, {%8,%9}, {%0,%1,%2,%3};" \
        : "+f"((d)[0]), "+f"((d)[1]), "+f"((d)[2]), "+f"((d)[3]) \
        : "r"((a)[0]), "r"((a)[1]), "r"((a)[2]), "r"((a)[3]), "r"(b0), "r"(b1))

__device__ __forceinline__ int swz_word36(int o, int kp) {
    int ks = kp >> 3, j = kp & 7;
    return o * ROWW + ks * 8 + 2 * ((j & 3) ^ ((o >> 2) & 3)) + (j >> 2);
}

// ---------------------------------------------------------------------------
// Prep: bake all bf16-split swizzled B images.
// ---------------------------------------------------------------------------
__global__ void prep_kernel(const float* __restrict__ w,
                            const float* __restrict__ ow,
                            const float* __restrict__ mw)
{
    int i = blockIdx.x * 256 + threadIdx.x;
    if (i < 9 * 2048) {                 // deform: 9 x 64 o x 32 kp
        int k  = i >> 11;
        int r  = i & 2047;
        int o  = r >> 5;
        int kp = r & 31;
        int c0 = 2 * kp;
        float v0 = w[o * 576 + c0 * 9 + k];
        float v1 = w[o * 576 + (c0 + 1) * 9 + k];
        float h0, l0, h1, l1;
        bfsplit(v0, h0, l0); bfsplit(v1, h1, l1);
        int word = swz_word36(o, kp);
        g_wbh[k * (64 * ROWW) + word] = bfpack(h0, h1);
        g_wbl[k * (64 * ROWW) + word] = bfpack(l0, l1);
    }
    int j = i - 9 * 2048;
    if (j >= 0 && j < 9 * 768) {        // offset conv
        int k  = j / 768;
        int r  = j % 768;
        int o  = r >> 5;
        int kp = r & 31;
        int c0 = 2 * kp;
        float v0 = (o < 18) ? ow[o * 576 + c0 * 9 + k] : 0.f;
        float v1 = (o < 18) ? ow[o * 576 + (c0 + 1) * 9 + k] : 0.f;
        float h0, l0, h1, l1;
        bfsplit(v0, h0, l0); bfsplit(v1, h1, l1);
        int word = swz_word36(o, kp);
        g_wboh[k * (24 * ROWW) + word] = bfpack(h0, h1);
        g_wbol[k * (24 * ROWW) + word] = bfpack(l0, l1);
    }
    int l = j - 9 * 768;
    if (l >= 0 && l < 9 * 512) {        // mod conv
        int k  = l / 512;
        int r  = l % 512;
        int o  = r >> 5;
        int kp = r & 31;
        int c0 = 2 * kp;
        float v0 = (o < 9) ? mw[o * 576 + c0 * 9 + k] : 0.f;
        float v1 = (o < 9) ? mw[o * 576 + (c0 + 1) * 9 + k] : 0.f;
        float h0, l0, h1, l1;
        bfsplit(v0, h0, l0); bfsplit(v1, h1, l1);
        int word = swz_word36(o, kp);
        g_wbmh[k * (16 * ROWW) + word] = bfpack(h0, h1);
        g_wbml[k * (16 * ROWW) + word] = bfpack(l0, l1);
    }
}

// ---------------------------------------------------------------------------
// Kernel 1: offset+mod convs (R12 form, unchanged).
// ---------------------------------------------------------------------------
#define A_HI  0
#define A_LO  (A_HI + 128 * ROWW)
#define BO_HI (A_LO + 128 * ROWW)
#define BO_LO (BO_HI + 24 * ROWW)
#define BM_HI (BO_LO + 24 * ROWW)
#define BM_LO (BM_HI + 16 * ROWW)
#define OM_WORDS (BM_LO + 16 * ROWW)    // 12096 words = 48384 B

__global__ __launch_bounds__(128, 4)
void offmask_kernel(const float* __restrict__ omap, const float* __restrict__ mmap,
                    const float* __restrict__ obias, const float* __restrict__ mbias)
{
    extern __shared__ uint32_t smu[];

    const int tid  = threadIdx.x;
    const int lane = tid & 31;
    const int warp = tid >> 5;
    const int g    = lane >> 2;
    const int tg   = lane & 3;

    const int b    = blockIdx.x >> 7;
    const int row  = blockIdx.x & 127;
    const int pix  = tid;
    const int swzp = (pix >> 2) & 3;

    const float* ob = omap + (size_t)b * Cc * HW;
    const float* mb = mmap + (size_t)b * Cc * HW;

    float d1[2][3][4];
    float d2[2][2][4];
#pragma unroll
    for (int mt = 0; mt < 2; mt++) {
#pragma unroll
        for (int nt = 0; nt < 3; nt++)
#pragma unroll
            for (int r = 0; r < 4; r++) d1[mt][nt][r] = 0.f;
#pragma unroll
        for (int nt = 0; nt < 2; nt++)
#pragma unroll
            for (int r = 0; r < 4; r++) d2[mt][nt][r] = 0.f;
    }

#pragma unroll 1
    for (int k = 0; k < 9; k++) {
        const int ki = k / 3, kj = k % 3;
        const int py = row - 1 + ki;
        const int px = pix - 1 + kj;
        const bool valid = ((unsigned)py < (unsigned)Hh) & ((unsigned)px < (unsigned)Ww);

        // ---- PASS 1: offset conv ----
        __syncthreads();
        {
            const uint4* soh = (const uint4*)&g_wboh[k * (24 * ROWW)];
            const uint4* sol = (const uint4*)&g_wbol[k * (24 * ROWW)];
            const uint4* smh = (const uint4*)&g_wbmh[k * (16 * ROWW)];
            const uint4* sml = (const uint4*)&g_wbml[k * (16 * ROWW)];
#pragma unroll
            for (int i = tid; i < 216; i += 128) {
                ((uint4*)&smu[BO_HI])[i] = soh[i];
                ((uint4*)&smu[BO_LO])[i] = sol[i];
            }
#pragma unroll
            for (int i = tid; i < 144; i += 128) {
                ((uint4*)&smu[BM_HI])[i] = smh[i];
                ((uint4*)&smu[BM_LO])[i] = sml[i];
            }
        }
        {
            const float* qo = ob + py * Ww + px;
#pragma unroll
            for (int ks = 0; ks < 4; ks++) {
#pragma unroll
                for (int kp0 = 0; kp0 < 4; kp0++) {
                    const int cA = 16 * ks + 2 * kp0;
                    const int cs[4] = { cA, cA + 1, cA + 8, cA + 9 };
                    float so[4];
#pragma unroll
                    for (int j = 0; j < 4; j++)
                        so[j] = valid ? __ldg(qo + cs[j] * HW) : 0.f;
                    float h[4], l[4];
#pragma unroll
                    for (int j = 0; j < 4; j++) bfsplit(so[j], h[j], l[j]);
                    const int wbase = pix * ROWW + ks * 8 + 2 * (kp0 ^ swzp);
                    *(uint2*)&smu[A_HI + wbase] = make_uint2(bfpack(h[0], h[1]), bfpack(h[2], h[3]));
                    *(uint2*)&smu[A_LO + wbase] = make_uint2(bfpack(l[0], l[1]), bfpack(l[2], l[3]));
                }
            }
        }
        __syncthreads();
#pragma unroll
        for (int ks = 0; ks < 4; ks++) {
            uint32_t ah[2][4], al[2][4];
#pragma unroll
            for (int mt = 0; mt < 2; mt++) {
                const int r0 = warp * 32 + mt * 16 + g;
                const int r1 = r0 + 8;
                const int w0 = r0 * ROWW + ks * 8 + 2 * (tg ^ ((r0 >> 2) & 3));
                const int w1 = r1 * ROWW + ks * 8 + 2 * (tg ^ ((r1 >> 2) & 3));
                uint2 H0 = *(const uint2*)&smu[A_HI + w0];
                uint2 H1 = *(const uint2*)&smu[A_HI + w1];
                uint2 L0 = *(const uint2*)&smu[A_LO + w0];
                uint2 L1 = *(const uint2*)&smu[A_LO + w1];
                ah[mt][0] = H0.x; ah[mt][1] = H1.x; ah[mt][2] = H0.y; ah[mt][3] = H1.y;
                al[mt][0] = L0.x; al[mt][1] = L1.x; al[mt][2] = L0.y; al[mt][3] = L1.y;
            }
#pragma unroll
            for (int nt = 0; nt < 3; nt++) {
                const int o  = nt * 8 + g;
                const int wb = o * ROWW + ks * 8 + 2 * (tg ^ ((o >> 2) & 3));
                uint2 bh = *(const uint2*)&smu[BO_HI + wb];
                uint2 bl = *(const uint2*)&smu[BO_LO + wb];
#pragma unroll
                for (int mt = 0; mt < 2; mt++) {
                    MMA_BF16(d1[mt][nt], ah[mt], bh.x, bh.y);
                    MMA_BF16(d1[mt][nt], al[mt], bh.x, bh.y);
                    MMA_BF16(d1[mt][nt], ah[mt], bl.x, bl.y);
                }
            }
        }

        // ---- PASS 2: mod conv ----
        __syncthreads();
        {
            const float* qm = mb + py * Ww + px;
#pragma unroll
            for (int ks = 0; ks < 4; ks++) {
#pragma unroll
                for (int kp0 = 0; kp0 < 4; kp0++) {
                    const int cA = 16 * ks + 2 * kp0;
                    const int cs[4] = { cA, cA + 1, cA + 8, cA + 9 };
                    float sm[4];
#pragma unroll
                    for (int j = 0; j < 4; j++)
                        sm[j] = valid ? __ldg(qm + cs[j] * HW) : 0.f;
                    float h[4], l[4];
#pragma unroll
                    for (int j = 0; j < 4; j++) bfsplit(sm[j], h[j], l[j]);
                    const int wbase = pix * ROWW + ks * 8 + 2 * (kp0 ^ swzp);
                    *(uint2*)&smu[A_HI + wbase] = make_uint2(bfpack(h[0], h[1]), bfpack(h[2], h[3]));
                    *(uint2*)&smu[A_LO + wbase] = make_uint2(bfpack(l[0], l[1]), bfpack(l[2], l[3]));
                }
            }
        }
        __syncthreads();
#pragma unroll
        for (int ks = 0; ks < 4; ks++) {
            uint32_t ah[2][4], al[2][4];
#pragma unroll
            for (int mt = 0; mt < 2; mt++) {
                const int r0 = warp * 32 + mt * 16 + g;
                const int r1 = r0 + 8;
                const int w0 = r0 * ROWW + ks * 8 + 2 * (tg ^ ((r0 >> 2) & 3));
                const int w1 = r1 * ROWW + ks * 8 + 2 * (tg ^ ((r1 >> 2) & 3));
                uint2 H0 = *(const uint2*)&smu[A_HI + w0];
                uint2 H1 = *(const uint2*)&smu[A_HI + w1];
                uint2 L0 = *(const uint2*)&smu[A_LO + w0];
                uint2 L1 = *(const uint2*)&smu[A_LO + w1];
                ah[mt][0] = H0.x; ah[mt][1] = H1.x; ah[mt][2] = H0.y; ah[mt][3] = H1.y;
                al[mt][0] = L0.x; al[mt][1] = L1.x; al[mt][2] = L0.y; al[mt][3] = L1.y;
            }
#pragma unroll
            for (int nt = 0; nt < 2; nt++) {
                const int o  = nt * 8 + g;
                const int wb = o * ROWW + ks * 8 + 2 * (tg ^ ((o >> 2) & 3));
                uint2 bh = *(const uint2*)&smu[BM_HI + wb];
                uint2 bl = *(const uint2*)&smu[BM_LO + wb];
#pragma unroll
                for (int mt = 0; mt < 2; mt++) {
                    MMA_BF16(d2[mt][nt], ah[mt], bh.x, bh.y);
                    MMA_BF16(d2[mt][nt], al[mt], bh.x, bh.y);
                    MMA_BF16(d2[mt][nt], ah[mt], bl.x, bl.y);
                }
            }
        }
    }

    // ---- epilogue ----
    float* S = g_scratch + (size_t)b * 27 * HW + row * Ww;
#pragma unroll
    for (int mt = 0; mt < 2; mt++) {
        const int r0 = warp * 32 + mt * 16 + g;
        const int r1 = r0 + 8;
#pragma unroll
        for (int nt = 0; nt < 3; nt++) {
            const int t0 = nt * 8 + tg * 2;
#pragma unroll
            for (int e = 0; e < 2; e++) {
                const int t = t0 + e;
                if (t < 18) {
                    const int plane = (t & 1) ? (9 + (t >> 1)) : (t >> 1);
                    const float bias = __ldg(&obias[t]);
                    S[plane * HW + r0] = d1[mt][nt][e]     + bias;
                    S[plane * HW + r1] = d1[mt][nt][e + 2] + bias;
                }
            }
        }
#pragma unroll
        for (int nt = 0; nt < 2; nt++) {
            const int t0 = nt * 8 + tg * 2;
#pragma unroll
            for (int e = 0; e < 2; e++) {
                const int t = t0 + e;
                if (t < 9) {
                    const float bias = __ldg(&mbias[t]);
                    float z0 = d2[mt][nt][e]     + bias;
                    float z1 = d2[mt][nt][e + 2] + bias;
                    S[(18 + t) * HW + r0] = 2.0f / (1.0f + expf(-z0));
                    S[(18 + t) * HW + r1] = 2.0f / (1.0f + expf(-z1));
                }
            }
        }
    }
}

// ---------------------------------------------------------------------------
// Kernel 2: deform conv, warp-specialized pipeline with 8 producer warps.
// 512 threads: warps 0-7 = producers (256 thr: pixel = tid&127, channel-half
// = tid>>7, 32 ch each), warps 8-15 = consumers (1 m-tile of 16 rows each).
// A/B double-buffered (110.6 KB, 2 CTAs/SM); launch_bounds(512,2) -> 64 regs.
// One __syncthreads per tap: MMA(tap k, buf k&1) overlaps sample(tap k+1).
// ---------------------------------------------------------------------------
#define DA_HI(bu)  ((bu) * 9216)
#define DA_LO(bu)  (DA_HI(bu) + 128 * ROWW)
#define DB_HI(bu)  (18432 + (bu) * 4608)
#define DB_LO(bu)  (DB_HI(bu) + 64 * ROWW)
#define DSM_WORDS  27648                   // 110592 B

__device__ __forceinline__ void deform_sample_tap(
    uint32_t* smu, const float* S, const float* xb,
    int row, int ptid, int t, int bu)
{
    const int pix  = ptid & 127;
    const int half = ptid >> 7;
    const int p    = row * Ww + pix;
    const int swzp = (pix >> 2) & 3;

    // stage B image for tap t (576 uint4 over 256 producer threads)
    {
        const uint4* sh = (const uint4*)&g_wbh[t * (64 * ROWW)];
        const uint4* sl = (const uint4*)&g_wbl[t * (64 * ROWW)];
        uint4* dh = (uint4*)&smu[DB_HI(bu)];
        uint4* dl = (uint4*)&smu[DB_LO(bu)];
#pragma unroll
        for (int i = ptid; i < 576; i += 256) {
            dh[i] = sh[i];
            dl[i] = sl[i];
        }
    }

    // tap descriptor (computed by both halves; cheap)
    const float dy = S[t * HW + p];
    const float dx = S[(9 + t) * HW + p];
    const float m  = S[(18 + t) * HW + p];
    const float py = dy + (float)(row - 1 + t / 3);
    const float px = dx + (float)(pix - 1 + t % 3);
    const float fy = floorf(py), fx = floorf(px);
    const int y0 = (int)fy, x0 = (int)fx;
    const int y1 = y0 + 1,  x1 = x0 + 1;
    const float wy = py - fy, wx = px - fx;

    const bool vy0 = ((unsigned)y0 < (unsigned)Hh);
    const bool vy1 = ((unsigned)y1 < (unsigned)Hh);
    const bool vx0 = ((unsigned)x0 < (unsigned)Ww);
    const bool vx1 = ((unsigned)x1 < (unsigned)Ww);
    const int y0c = min(max(y0, 0), Hh - 1);
    const int y1c = min(max(y1, 0), Hh - 1);
    const int x0c = min(max(x0, 0), Ww - 1);
    const int x1c = min(max(x1, 0), Ww - 1);

    float c00 = (1.f - wy) * (1.f - wx) * m; c00 = (vy0 & vx0) ? c00 : 0.f;
    float c01 = (1.f - wy) * wx         * m; c01 = (vy0 & vx1) ? c01 : 0.f;
    float c10 = wy * (1.f - wx)         * m; c10 = (vy1 & vx0) ? c10 : 0.f;
    float c11 = wy * wx                 * m; c11 = (vy1 & vx1) ? c11 : 0.f;

    const float* q00 = xb + y0c * Ww + x0c;
    const float* q01 = xb + y0c * Ww + x1c;
    const float* q10 = xb + y1c * Ww + x0c;
    const float* q11 = xb + y1c * Ww + x1c;

    // this half owns k-steps {2*half, 2*half+1} = channels [32*half, 32*half+32)
#pragma unroll
    for (int kk = 0; kk < 2; kk++) {
        const int ks = 2 * half + kk;
#pragma unroll
        for (int kp0 = 0; kp0 < 4; kp0++) {
            const int cA = 16 * ks + 2 * kp0;
            const int cs[4] = { cA, cA + 1, cA + 8, cA + 9 };
            float s[4];
#pragma unroll
            for (int j = 0; j < 4; j++) {
                const int c = cs[j];
                float v = __ldg(q00 + c * HW) * c00;
                v = fmaf(__ldg(q01 + c * HW), c01, v);
                v = fmaf(__ldg(q10 + c * HW), c10, v);
                v = fmaf(__ldg(q11 + c * HW), c11, v);
                s[j] = v;
            }
            float h0, l0, h1, l1, h2, l2, h3, l3;
            bfsplit(s[0], h0, l0); bfsplit(s[1], h1, l1);
            bfsplit(s[2], h2, l2); bfsplit(s[3], h3, l3);
            const int wbase = pix * ROWW + ks * 8 + 2 * (kp0 ^ swzp);
            *(uint2*)&smu[DA_HI(bu) + wbase] = make_uint2(bfpack(h0, h1), bfpack(h2, h3));
            *(uint2*)&smu[DA_LO(bu) + wbase] = make_uint2(bfpack(l0, l1), bfpack(l2, l3));
        }
    }
}

__global__ __launch_bounds__(512, 2)
void deform_kernel(const float* __restrict__ x, float* __restrict__ out)
{
    extern __shared__ uint32_t smu[];

    const int tid  = threadIdx.x;
    const int lane = tid & 31;
    const int warp = tid >> 5;
    const int g    = lane >> 2;
    const int tg   = lane & 3;

    const int b   = blockIdx.x >> 7;
    const int row = blockIdx.x & 127;

    const bool producer = (warp < 8);

    float acc[8][4];
#pragma unroll
    for (int nt = 0; nt < 8; nt++)
#pragma unroll
        for (int r = 0; r < 4; r++) acc[nt][r] = 0.f;

    const float* S  = g_scratch + (size_t)b * 27 * HW;
    const float* xb = x + (size_t)b * Cc * HW;

    // prologue: producers fill buffer 0 with tap 0
    if (producer) deform_sample_tap(smu, S, xb, row, tid, 0, 0);

#pragma unroll 1
    for (int k = 0; k < 9; k++) {
        __syncthreads();
        if (producer) {
            if (k < 8) deform_sample_tap(smu, S, xb, row, tid, k + 1, (k + 1) & 1);
        } else {
            const int cw = warp - 8;          // 0..7, m-tile rows [cw*16, cw*16+16)
            const int bu = k & 1;
#pragma unroll
            for (int ks = 0; ks < 4; ks++) {
                uint32_t ah[4], al[4];
                {
                    const int r0 = cw * 16 + g;
                    const int r1 = r0 + 8;
                    const int w0 = r0 * ROWW + ks * 8 + 2 * (tg ^ ((r0 >> 2) & 3));
                    const int w1 = r1 * ROWW + ks * 8 + 2 * (tg ^ ((r1 >> 2) & 3));
                    uint2 H0 = *(const uint2*)&smu[DA_HI(bu) + w0];
                    uint2 H1 = *(const uint2*)&smu[DA_HI(bu) + w1];
                    uint2 L0 = *(const uint2*)&smu[DA_LO(bu) + w0];
                    uint2 L1 = *(const uint2*)&smu[DA_LO(bu) + w1];
                    ah[0] = H0.x; ah[1] = H1.x; ah[2] = H0.y; ah[3] = H1.y;
                    al[0] = L0.x; al[1] = L1.x; al[2] = L0.y; al[3] = L1.y;
                }
#pragma unroll
                for (int nt = 0; nt < 8; nt++) {
                    const int o  = nt * 8 + g;
                    const int wb = o * ROWW + ks * 8 + 2 * (tg ^ ((o >> 2) & 3));
                    uint2 bh = *(const uint2*)&smu[DB_HI(bu) + wb];
                    uint2 bl = *(const uint2*)&smu[DB_LO(bu) + wb];
                    MMA_BF16(acc[nt], ah, bh.x, bh.y);
                    MMA_BF16(acc[nt], al, bh.x, bh.y);
                    MMA_BF16(acc[nt], ah, bl.x, bl.y);
                }
            }
        }
    }

    // epilogue: consumers write D fragments to out[b][o][row][x]
    if (!producer) {
        const int cw = warp - 8;
        float* ob = out + (size_t)b * Oo * HW + row * Ww;
        const int r0 = cw * 16 + g;
        const int r1 = r0 + 8;
#pragma unroll
        for (int nt = 0; nt < 8; nt++) {
            const int o0 = nt * 8 + tg * 2;
            ob[(o0)     * HW + r0] = acc[nt][0];
            ob[(o0 + 1) * HW + r0] = acc[nt][1];
            ob[(o0)     * HW + r1] = acc[nt][2];
            ob[(o0 + 1) * HW + r1] = acc[nt][3];
        }
    }
}

// ---------------------------------------------------------------------------

extern "C" void kernel_launch(void* const* d_in, const int* in_sizes, int n_in,
                              void* d_out, int out_size)
{
    const float* x     = (const float*)d_in[0];
    const float* omap  = (const float*)d_in[1];
    const float* mmap  = (const float*)d_in[2];
    const float* ow    = (const float*)d_in[3];
    const float* obias = (const float*)d_in[4];
    const float* mw    = (const float*)d_in[5];
    const float* mbias = (const float*)d_in[6];
    const float* w     = (const float*)d_in[7];
    float* out = (float*)d_out;

    const int prep_total = 9 * 2048 + 9 * 768 + 9 * 512;   // 29952
    prep_kernel<<<(prep_total + 255) / 256, 256>>>(w, ow, mw);

    dim3 grid(Bb * Hh);     // 512 blocks, 1 image row each

    const int om_smem = OM_WORDS * (int)sizeof(uint32_t);  // 48384
    cudaFuncSetAttribute(offmask_kernel, cudaFuncAttributeMaxDynamicSharedMemorySize, om_smem);
    offmask_kernel<<<grid, 128, om_smem>>>(omap, mmap, obias, mbias);

    const int df_smem = DSM_WORDS * (int)sizeof(uint32_t); // 110592
    cudaFuncSetAttribute(deform_kernel, cudaFuncAttributeMaxDynamicSharedMemorySize, df_smem);
    deform_kernel<<<grid, 512, df_smem>>>(x, out);
}

// round 16
// speedup vs baseline: 1.2030x; 1.2030x over previous
#include <cuda_runtime.h>
#include <cuda_bf16.h>
#include <math.h>
#include <stdint.h>

#define HW   (128 * 128)
#define Hh   128
#define Ww   128
#define Bb   4
#define Cc   64
#define Oo   64

// Scratch: offsets/mask planes [B][27][H][W]  (0..8 dy_k, 9..17 dx_k, 18..26 mask_k)
__device__ float g_scratch[Bb * 27 * HW];

#define ROWW 36
// deform weight images (tap-major)
__device__ __align__(16) uint32_t g_wbh[9 * 64 * ROWW];
__device__ __align__(16) uint32_t g_wbl[9 * 64 * ROWW];
// offmask weight images
__device__ __align__(16) uint32_t g_wboh[9 * 24 * ROWW];
__device__ __align__(16) uint32_t g_wbol[9 * 24 * ROWW];
__device__ __align__(16) uint32_t g_wbmh[9 * 16 * ROWW];
__device__ __align__(16) uint32_t g_wbml[9 * 16 * ROWW];

// ---------------- helpers ----------------
__device__ __forceinline__ uint32_t bfpack(float a, float b) {
    __nv_bfloat162 t = __floats2bfloat162_rn(a, b);
    return *(uint32_t*)&t;
}
// rn split (used in prep only, for B images)
__device__ __forceinline__ void bfsplit(float s, float &hi, float &lo) {
    hi = __bfloat162float(__float2bfloat16(s));
    lo = s - hi;
}
// truncating split for A (sampler fast path): hi = s & 0xffff0000
__device__ __forceinline__ float truncbf(float s) {
    return __uint_as_float(__float_as_uint(s) & 0xffff0000u);
}
// pack truncated-bf16 of (s0, s1) into one word: low half = hi16(s0)
__device__ __forceinline__ uint32_t packhi(float s0, float s1) {
    return __byte_perm(__float_as_uint(s0), __float_as_uint(s1), 0x7632);
}

#define MMA_BF16(d, a, b0, b1) \
    asm volatile("mma.sync.aligned.m16n8k16.row.col.f32.bf16.bf16.f32 " \
        "{%0,%1,%2,%3}, {%4,%5,%6,%7}, {%8,%9}, {%0,%1,%2,%3};" \
        : "+f"((d)[0]), "+f"((d)[1]), "+f"((d)[2]), "+f"((d)[3]) \
        : "r"((a)[0]), "r"((a)[1]), "r"((a)[2]), "r"((a)[3]), "r"(b0), "r"(b1))

__device__ __forceinline__ int swz_word36(int o, int kp) {
    int ks = kp >> 3, j = kp & 7;
    return o * ROWW + ks * 8 + 2 * ((j & 3) ^ ((o >> 2) & 3)) + (j >> 2);
}

// ---------------------------------------------------------------------------
// Prep: bake all bf16-split (rn) swizzled B images.
// ---------------------------------------------------------------------------
__global__ void prep_kernel(const float* __restrict__ w,
                            const float* __restrict__ ow,
                            const float* __restrict__ mw)
{
    int i = blockIdx.x * 256 + threadIdx.x;
    if (i < 9 * 2048) {                 // deform: 9 x 64 o x 32 kp
        int k  = i >> 11;
        int r  = i & 2047;
        int o  = r >> 5;
        int kp = r & 31;
        int c0 = 2 * kp;
        float v0 = w[o * 576 + c0 * 9 + k];
        float v1 = w[o * 576 + (c0 + 1) * 9 + k];
        float h0, l0, h1, l1;
        bfsplit(v0, h0, l0); bfsplit(v1, h1, l1);
        int word = swz_word36(o, kp);
        g_wbh[k * (64 * ROWW) + word] = bfpack(h0, h1);
        g_wbl[k * (64 * ROWW) + word] = bfpack(l0, l1);
    }
    int j = i - 9 * 2048;
    if (j >= 0 && j < 9 * 768) {        // offset conv
        int k  = j / 768;
        int r  = j % 768;
        int o  = r >> 5;
        int kp = r & 31;
        int c0 = 2 * kp;
        float v0 = (o < 18) ? ow[o * 576 + c0 * 9 + k] : 0.f;
        float v1 = (o < 18) ? ow[o * 576 + (c0 + 1) * 9 + k] : 0.f;
        float h0, l0, h1, l1;
        bfsplit(v0, h0, l0); bfsplit(v1, h1, l1);
        int word = swz_word36(o, kp);
        g_wboh[k * (24 * ROWW) + word] = bfpack(h0, h1);
        g_wbol[k * (24 * ROWW) + word] = bfpack(l0, l1);
    }
    int l = j - 9 * 768;
    if (l >= 0 && l < 9 * 512) {        // mod conv
        int k  = l / 512;
        int r  = l % 512;
        int o  = r >> 5;
        int kp = r & 31;
        int c0 = 2 * kp;
        float v0 = (o < 9) ? mw[o * 576 + c0 * 9 + k] : 0.f;
        float v1 = (o < 9) ? mw[o * 576 + (c0 + 1) * 9 + k] : 0.f;
        float h0, l0, h1, l1;
        bfsplit(v0, h0, l0); bfsplit(v1, h1, l1);
        int word = swz_word36(o, kp);
        g_wbmh[k * (16 * ROWW) + word] = bfpack(h0, h1);
        g_wbml[k * (16 * ROWW) + word] = bfpack(l0, l1);
    }
}

// ---------------------------------------------------------------------------
// Kernel 1: offset+mod convs as bf16 MMA GEMMs, half-tap passes sharing one
// A tile pair (R11 structure, ROWW=36, truncating A-split).  4 CTAs/SM.
// ---------------------------------------------------------------------------
#define A_HI  0
#define A_LO  (A_HI + 128 * ROWW)
#define BO_HI (A_LO + 128 * ROWW)
#define BO_LO (BO_HI + 24 * ROWW)
#define BM_HI (BO_LO + 24 * ROWW)
#define BM_LO (BM_HI + 16 * ROWW)
#define OM_WORDS (BM_LO + 16 * ROWW)    // 12096 words = 48384 B

__global__ __launch_bounds__(128, 4)
void offmask_kernel(const float* __restrict__ omap, const float* __restrict__ mmap,
                    const float* __restrict__ obias, const float* __restrict__ mbias)
{
    extern __shared__ uint32_t smu[];

    const int tid  = threadIdx.x;
    const int lane = tid & 31;
    const int warp = tid >> 5;
    const int g    = lane >> 2;
    const int tg   = lane & 3;

    const int b    = blockIdx.x >> 7;
    const int row  = blockIdx.x & 127;
    const int pix  = tid;
    const int swzp = (pix >> 2) & 3;

    const float* ob = omap + (size_t)b * Cc * HW;
    const float* mb = mmap + (size_t)b * Cc * HW;

    float d1[2][3][4];
    float d2[2][2][4];
#pragma unroll
    for (int mt = 0; mt < 2; mt++) {
#pragma unroll
        for (int nt = 0; nt < 3; nt++)
#pragma unroll
            for (int r = 0; r < 4; r++) d1[mt][nt][r] = 0.f;
#pragma unroll
        for (int nt = 0; nt < 2; nt++)
#pragma unroll
            for (int r = 0; r < 4; r++) d2[mt][nt][r] = 0.f;
    }

#pragma unroll 1
    for (int k = 0; k < 9; k++) {
        const int ki = k / 3, kj = k % 3;
        const int py = row - 1 + ki;
        const int px = pix - 1 + kj;
        const bool valid = ((unsigned)py < (unsigned)Hh) & ((unsigned)px < (unsigned)Ww);

        // ---- PASS 1: offset conv ----
        __syncthreads();
        {
            const uint4* soh = (const uint4*)&g_wboh[k * (24 * ROWW)];
            const uint4* sol = (const uint4*)&g_wbol[k * (24 * ROWW)];
            const uint4* smh = (const uint4*)&g_wbmh[k * (16 * ROWW)];
            const uint4* sml = (const uint4*)&g_wbml[k * (16 * ROWW)];
#pragma unroll
            for (int i = tid; i < 216; i += 128) {
                ((uint4*)&smu[BO_HI])[i] = soh[i];
                ((uint4*)&smu[BO_LO])[i] = sol[i];
            }
#pragma unroll
            for (int i = tid; i < 144; i += 128) {
                ((uint4*)&smu[BM_HI])[i] = smh[i];
                ((uint4*)&smu[BM_LO])[i] = sml[i];
            }
        }
        {
            const float* qo = ob + py * Ww + px;
#pragma unroll
            for (int ks = 0; ks < 4; ks++) {
#pragma unroll
                for (int kp0 = 0; kp0 < 4; kp0++) {
                    const int cA = 16 * ks + 2 * kp0;
                    const int cs[4] = { cA, cA + 1, cA + 8, cA + 9 };
                    float s[4];
#pragma unroll
                    for (int j = 0; j < 4; j++)
                        s[j] = valid ? __ldg(qo + cs[j] * HW) : 0.f;
                    float l0 = s[0] - truncbf(s[0]);
                    float l1 = s[1] - truncbf(s[1]);
                    float l2 = s[2] - truncbf(s[2]);
                    float l3 = s[3] - truncbf(s[3]);
                    const int wbase = pix * ROWW + ks * 8 + 2 * (kp0 ^ swzp);
                    *(uint2*)&smu[A_HI + wbase] = make_uint2(packhi(s[0], s[1]), packhi(s[2], s[3]));
                    *(uint2*)&smu[A_LO + wbase] = make_uint2(bfpack(l0, l1), bfpack(l2, l3));
                }
            }
        }
        __syncthreads();
#pragma unroll
        for (int ks = 0; ks < 4; ks++) {
            uint32_t ah[2][4], al[2][4];
#pragma unroll
            for (int mt = 0; mt < 2; mt++) {
                const int r0 = warp * 32 + mt * 16 + g;
                const int r1 = r0 + 8;
                const int w0 = r0 * ROWW + ks * 8 + 2 * (tg ^ ((r0 >> 2) & 3));
                const int w1 = r1 * ROWW + ks * 8 + 2 * (tg ^ ((r1 >> 2) & 3));
                uint2 H0 = *(const uint2*)&smu[A_HI + w0];
                uint2 H1 = *(const uint2*)&smu[A_HI + w1];
                uint2 L0 = *(const uint2*)&smu[A_LO + w0];
                uint2 L1 = *(const uint2*)&smu[A_LO + w1];
                ah[mt][0] = H0.x; ah[mt][1] = H1.x; ah[mt][2] = H0.y; ah[mt][3] = H1.y;
                al[mt][0] = L0.x; al[mt][1] = L1.x; al[mt][2] = L0.y; al[mt][3] = L1.y;
            }
#pragma unroll
            for (int nt = 0; nt < 3; nt++) {
                const int o  = nt * 8 + g;
                const int wb = o * ROWW + ks * 8 + 2 * (tg ^ ((o >> 2) & 3));
                uint2 bh = *(const uint2*)&smu[BO_HI + wb];
                uint2 bl = *(const uint2*)&smu[BO_LO + wb];
#pragma unroll
                for (int mt = 0; mt < 2; mt++) {
                    MMA_BF16(d1[mt][nt], ah[mt], bh.x, bh.y);
                    MMA_BF16(d1[mt][nt], al[mt], bh.x, bh.y);
                    MMA_BF16(d1[mt][nt], ah[mt], bl.x, bl.y);
                }
            }
        }

        // ---- PASS 2: mod conv ----
        __syncthreads();
        {
            const float* qm = mb + py * Ww + px;
#pragma unroll
            for (int ks = 0; ks < 4; ks++) {
#pragma unroll
                for (int kp0 = 0; kp0 < 4; kp0++) {
                    const int cA = 16 * ks + 2 * kp0;
                    const int cs[4] = { cA, cA + 1, cA + 8, cA + 9 };
                    float s[4];
#pragma unroll
                    for (int j = 0; j < 4; j++)
                        s[j] = valid ? __ldg(qm + cs[j] * HW) : 0.f;
                    float l0 = s[0] - truncbf(s[0]);
                    float l1 = s[1] - truncbf(s[1]);
                    float l2 = s[2] - truncbf(s[2]);
                    float l3 = s[3] - truncbf(s[3]);
                    const int wbase = pix * ROWW + ks * 8 + 2 * (kp0 ^ swzp);
                    *(uint2*)&smu[A_HI + wbase] = make_uint2(packhi(s[0], s[1]), packhi(s[2], s[3]));
                    *(uint2*)&smu[A_LO + wbase] = make_uint2(bfpack(l0, l1), bfpack(l2, l3));
                }
            }
        }
        __syncthreads();
#pragma unroll
        for (int ks = 0; ks < 4; ks++) {
            uint32_t ah[2][4], al[2][4];
#pragma unroll
            for (int mt = 0; mt < 2; mt++) {
                const int r0 = warp * 32 + mt * 16 + g;
                const int r1 = r0 + 8;
                const int w0 = r0 * ROWW + ks * 8 + 2 * (tg ^ ((r0 >> 2) & 3));
                const int w1 = r1 * ROWW + ks * 8 + 2 * (tg ^ ((r1 >> 2) & 3));
                uint2 H0 = *(const uint2*)&smu[A_HI + w0];
                uint2 H1 = *(const uint2*)&smu[A_HI + w1];
                uint2 L0 = *(const uint2*)&smu[A_LO + w0];
                uint2 L1 = *(const uint2*)&smu[A_LO + w1];
                ah[mt][0] = H0.x; ah[mt][1] = H1.x; ah[mt][2] = H0.y; ah[mt][3] = H1.y;
                al[mt][0] = L0.x; al[mt][1] = L1.x; al[mt][2] = L0.y; al[mt][3] = L1.y;
            }
#pragma unroll
            for (int nt = 0; nt < 2; nt++) {
                const int o  = nt * 8 + g;
                const int wb = o * ROWW + ks * 8 + 2 * (tg ^ ((o >> 2) & 3));
                uint2 bh = *(const uint2*)&smu[BM_HI + wb];
                uint2 bl = *(const uint2*)&smu[BM_LO + wb];
#pragma unroll
                for (int mt = 0; mt < 2; mt++) {
                    MMA_BF16(d2[mt][nt], ah[mt], bh.x, bh.y);
                    MMA_BF16(d2[mt][nt], al[mt], bh.x, bh.y);
                    MMA_BF16(d2[mt][nt], ah[mt], bl.x, bl.y);
                }
            }
        }
    }

    // ---- epilogue ----
    float* S = g_scratch + (size_t)b * 27 * HW + row * Ww;
#pragma unroll
    for (int mt = 0; mt < 2; mt++) {
        const int r0 = warp * 32 + mt * 16 + g;
        const int r1 = r0 + 8;
#pragma unroll
        for (int nt = 0; nt < 3; nt++) {
            const int t0 = nt * 8 + tg * 2;
#pragma unroll
            for (int e = 0; e < 2; e++) {
                const int t = t0 + e;
                if (t < 18) {
                    const int plane = (t & 1) ? (9 + (t >> 1)) : (t >> 1);
                    const float bias = __ldg(&obias[t]);
                    S[plane * HW + r0] = d1[mt][nt][e]     + bias;
                    S[plane * HW + r1] = d1[mt][nt][e + 2] + bias;
                }
            }
        }
#pragma unroll
        for (int nt = 0; nt < 2; nt++) {
            const int t0 = nt * 8 + tg * 2;
#pragma unroll
            for (int e = 0; e < 2; e++) {
                const int t = t0 + e;
                if (t < 9) {
                    const float bias = __ldg(&mbias[t]);
                    float z0 = d2[mt][nt][e]     + bias;
                    float z1 = d2[mt][nt][e + 2] + bias;
                    S[(18 + t) * HW + r0] = 2.0f / (1.0f + expf(-z0));
                    S[(18 + t) * HW + r1] = 2.0f / (1.0f + expf(-z1));
                }
            }
        }
    }
}

// ---------------------------------------------------------------------------
// Kernel 2: deformable conv bf16 MMA implicit GEMM (R11 structure, ROWW=36),
// with truncating A-split + next-tap descriptor prefetch.
// ---------------------------------------------------------------------------
#define SA_HI 0
#define SA_LO (SA_HI + 128 * ROWW)
#define SB_HI (SA_LO + 128 * ROWW)
#define SB_LO (SB_HI + 64 * ROWW)
#define SM_WORDS (SB_LO + 64 * ROWW)     // 13824 words = 55296 B

__global__ __launch_bounds__(128)
void deform_kernel(const float* __restrict__ x, float* __restrict__ out)
{
    extern __shared__ uint32_t smu[];

    const int tid  = threadIdx.x;
    const int lane = tid & 31;
    const int warp = tid >> 5;
    const int g    = lane >> 2;
    const int tg   = lane & 3;

    const int b   = blockIdx.x >> 7;
    const int row = blockIdx.x & 127;
    const int pix = tid;
    const int p   = row * Ww + pix;
    const int swzp = (pix >> 2) & 3;

    const float* S  = g_scratch + (size_t)b * 27 * HW;
    const float* xb = x + (size_t)b * Cc * HW;

    float acc[2][8][4];
#pragma unroll
    for (int mt = 0; mt < 2; mt++)
#pragma unroll
        for (int nt = 0; nt < 8; nt++)
#pragma unroll
            for (int r = 0; r < 4; r++) acc[mt][nt][r] = 0.f;

    // prefetch tap 0 descriptor inputs
    float dy = S[p];
    float dx = S[9 * HW + p];
    float m  = S[18 * HW + p];

#pragma unroll 1
    for (int k = 0; k < 9; k++) {
        __syncthreads();

        {
            const uint4* sh = (const uint4*)&g_wbh[k * (64 * ROWW)];
            const uint4* sl = (const uint4*)&g_wbl[k * (64 * ROWW)];
            uint4* dh = (uint4*)&smu[SB_HI];
            uint4* dl = (uint4*)&smu[SB_LO];
#pragma unroll
            for (int i = tid; i < 576; i += 128) {
                dh[i] = sh[i];
                dl[i] = sl[i];
            }
        }

        const float py = dy + (float)(row - 1 + k / 3);
        const float px = dx + (float)(pix - 1 + k % 3);
        const float fy = floorf(py), fx = floorf(px);
        const int y0 = (int)fy, x0 = (int)fx;
        const int y1 = y0 + 1,  x1 = x0 + 1;
        const float wy = py - fy, wx = px - fx;

        const bool vy0 = ((unsigned)y0 < (unsigned)Hh);
        const bool vy1 = ((unsigned)y1 < (unsigned)Hh);
        const bool vx0 = ((unsigned)x0 < (unsigned)Ww);
        const bool vx1 = ((unsigned)x1 < (unsigned)Ww);
        const int y0c = min(max(y0, 0), Hh - 1);
        const int y1c = min(max(y1, 0), Hh - 1);
        const int x0c = min(max(x0, 0), Ww - 1);
        const int x1c = min(max(x1, 0), Ww - 1);

        float c00 = (1.f - wy) * (1.f - wx) * m; c00 = (vy0 & vx0) ? c00 : 0.f;
        float c01 = (1.f - wy) * wx         * m; c01 = (vy0 & vx1) ? c01 : 0.f;
        float c10 = wy * (1.f - wx)         * m; c10 = (vy1 & vx0) ? c10 : 0.f;
        float c11 = wy * wx                 * m; c11 = (vy1 & vx1) ? c11 : 0.f;

        const float* q00 = xb + y0c * Ww + x0c;
        const float* q01 = xb + y0c * Ww + x1c;
        const float* q10 = xb + y1c * Ww + x0c;
        const float* q11 = xb + y1c * Ww + x1c;

#pragma unroll
        for (int ks = 0; ks < 4; ks++) {
#pragma unroll
            for (int kp0 = 0; kp0 < 4; kp0++) {
                const int cA = 16 * ks + 2 * kp0;
                const int cs[4] = { cA, cA + 1, cA + 8, cA + 9 };
                float s[4];
#pragma unroll
                for (int j = 0; j < 4; j++) {
                    const int c = cs[j];
                    float v = __ldg(q00 + c * HW) * c00;
                    v = fmaf(__ldg(q01 + c * HW), c01, v);
                    v = fmaf(__ldg(q10 + c * HW), c10, v);
                    v = fmaf(__ldg(q11 + c * HW), c11, v);
                    s[j] = v;
                }
                float l0 = s[0] - truncbf(s[0]);
                float l1 = s[1] - truncbf(s[1]);
                float l2 = s[2] - truncbf(s[2]);
                float l3 = s[3] - truncbf(s[3]);
                const int wbase = pix * ROWW + ks * 8 + 2 * (kp0 ^ swzp);
                *(uint2*)&smu[SA_HI + wbase] = make_uint2(packhi(s[0], s[1]), packhi(s[2], s[3]));
                *(uint2*)&smu[SA_LO + wbase] = make_uint2(bfpack(l0, l1), bfpack(l2, l3));
            }
        }

        // prefetch next tap's descriptor inputs (overlaps sync + MMA)
        if (k < 8) {
            dy = S[(k + 1) * HW + p];
            dx = S[(9 + k + 1) * HW + p];
            m  = S[(18 + k + 1) * HW + p];
        }

        __syncthreads();

#pragma unroll
        for (int ks = 0; ks < 4; ks++) {
            uint32_t ah[2][4], al[2][4];
#pragma unroll
            for (int mt = 0; mt < 2; mt++) {
                const int r0 = warp * 32 + mt * 16 + g;
                const int r1 = r0 + 8;
                const int w0 = r0 * ROWW + ks * 8 + 2 * (tg ^ ((r0 >> 2) & 3));
                const int w1 = r1 * ROWW + ks * 8 + 2 * (tg ^ ((r1 >> 2) & 3));
                uint2 H0 = *(const uint2*)&smu[SA_HI + w0];
                uint2 H1 = *(const uint2*)&smu[SA_HI + w1];
                uint2 L0 = *(const uint2*)&smu[SA_LO + w0];
                uint2 L1 = *(const uint2*)&smu[SA_LO + w1];
                ah[mt][0] = H0.x; ah[mt][1] = H1.x; ah[mt][2] = H0.y; ah[mt][3] = H1.y;
                al[mt][0] = L0.x; al[mt][1] = L1.x; al[mt][2] = L0.y; al[mt][3] = L1.y;
            }
#pragma unroll
            for (int nt = 0; nt < 8; nt++) {
                const int o  = nt * 8 + g;
                const int wb = o * ROWW + ks * 8 + 2 * (tg ^ ((o >> 2) & 3));
                uint2 bh = *(const uint2*)&smu[SB_HI + wb];
                uint2 bl = *(const uint2*)&smu[SB_LO + wb];
#pragma unroll
                for (int mt = 0; mt < 2; mt++) {
                    MMA_BF16(acc[mt][nt], ah[mt], bh.x, bh.y);
                    MMA_BF16(acc[mt][nt], al[mt], bh.x, bh.y);
                    MMA_BF16(acc[mt][nt], ah[mt], bl.x, bl.y);
                }
            }
        }
    }

    float* ob = out + (size_t)b * Oo * HW + row * Ww;
#pragma unroll
    for (int mt = 0; mt < 2; mt++) {
        const int r0 = warp * 32 + mt * 16 + g;
        const int r1 = r0 + 8;
#pragma unroll
        for (int nt = 0; nt < 8; nt++) {
            const int o0 = nt * 8 + tg * 2;
            ob[(o0)     * HW + r0] = acc[mt][nt][0];
            ob[(o0 + 1) * HW + r0] = acc[mt][nt][1];
            ob[(o0)     * HW + r1] = acc[mt][nt][2];
            ob[(o0 + 1) * HW + r1] = acc[mt][nt][3];
        }
    }
}

// ---------------------------------------------------------------------------

extern "C" void kernel_launch(void* const* d_in, const int* in_sizes, int n_in,
                              void* d_out, int out_size)
{
    const float* x     = (const float*)d_in[0];
    const float* omap  = (const float*)d_in[1];
    const float* mmap  = (const float*)d_in[2];
    const float* ow    = (const float*)d_in[3];
    const float* obias = (const float*)d_in[4];
    const float* mw    = (const float*)d_in[5];
    const float* mbias = (const float*)d_in[6];
    const float* w     = (const float*)d_in[7];
    float* out = (float*)d_out;

    const int prep_total = 9 * 2048 + 9 * 768 + 9 * 512;   // 29952
    prep_kernel<<<(prep_total + 255) / 256, 256>>>(w, ow, mw);

    dim3 grid(Bb * Hh);     // 512 blocks, 1 image row each

    const int om_smem = OM_WORDS * (int)sizeof(uint32_t);  // 48384
    cudaFuncSetAttribute(offmask_kernel, cudaFuncAttributeMaxDynamicSharedMemorySize, om_smem);
    offmask_kernel<<<grid, 128, om_smem>>>(omap, mmap, obias, mbias);

    const int df_smem = SM_WORDS * (int)sizeof(uint32_t);  // 55296
    cudaFuncSetAttribute(deform_kernel, cudaFuncAttributeMaxDynamicSharedMemorySize, df_smem);
    deform_kernel<<<grid, 128, df_smem>>>(x, out);
}

// round 17
// speedup vs baseline: 1.2168x; 1.0115x over previous
#include <cuda_runtime.h>
#include <cuda_bf16.h>
#include <math.h>
#include <stdint.h>

#define HW   (128 * 128)
#define Hh   128
#define Ww   128
#define Bb   4
#define Cc   64
#define Oo   64

// Scratch: offsets/mask planes [B][27][H][W]  (0..8 dy_k, 9..17 dx_k, 18..26 mask_k)
__device__ float g_scratch[Bb * 27 * HW];

#define ROWW 36
// deform weight images (tap-major)
__device__ __align__(16) uint32_t g_wbh[9 * 64 * ROWW];
__device__ __align__(16) uint32_t g_wbl[9 * 64 * ROWW];
// offmask weight images
__device__ __align__(16) uint32_t g_wboh[9 * 24 * ROWW];
__device__ __align__(16) uint32_t g_wbol[9 * 24 * ROWW];
__device__ __align__(16) uint32_t g_wbmh[9 * 16 * ROWW];
__device__ __align__(16) uint32_t g_wbml[9 * 16 * ROWW];

// ---------------- helpers ----------------
__device__ __forceinline__ uint32_t bfpack(float a, float b) {
    __nv_bfloat162 t = __floats2bfloat162_rn(a, b);
    return *(uint32_t*)&t;
}
__device__ __forceinline__ void bfsplit(float s, float &hi, float &lo) {
    hi = __bfloat162float(__float2bfloat16(s));
    lo = s - hi;
}

#define MMA_BF16(d, a, b0, b1) \
    asm volatile("mma.sync.aligned.m16n8k16.row.col.f32.bf16.bf16.f32 " \
        "{%0,%1,%2,%3}, {%4,%5,%6,%7}, {%8,%9}, {%0,%1,%2,%3};" \
        : "+f"((d)[0]), "+f"((d)[1]), "+f"((d)[2]), "+f"((d)[3]) \
        : "r"((a)[0]), "r"((a)[1]), "r"((a)[2]), "r"((a)[3]), "r"(b0), "r"(b1))

__device__ __forceinline__ int swz_word36(int o, int kp) {
    int ks = kp >> 3, j = kp & 7;
    return o * ROWW + ks * 8 + 2 * ((j & 3) ^ ((o >> 2) & 3)) + (j >> 2);
}

// ---------------------------------------------------------------------------
// Prep: bake all bf16-split swizzled B images (R12 form).
// ---------------------------------------------------------------------------
__global__ void prep_kernel(const float* __restrict__ w,
                            const float* __restrict__ ow,
                            const float* __restrict__ mw)
{
    int i = blockIdx.x * 256 + threadIdx.x;
    if (i < 9 * 2048) {                 // deform: 9 x 64 o x 32 kp
        int k  = i >> 11;
        int r  = i & 2047;
        int o  = r >> 5;
        int kp = r & 31;
        int c0 = 2 * kp;
        float v0 = w[o * 576 + c0 * 9 + k];
        float v1 = w[o * 576 + (c0 + 1) * 9 + k];
        float h0, l0, h1, l1;
        bfsplit(v0, h0, l0); bfsplit(v1, h1, l1);
        int word = swz_word36(o, kp);
        g_wbh[k * (64 * ROWW) + word] = bfpack(h0, h1);
        g_wbl[k * (64 * ROWW) + word] = bfpack(l0, l1);
    }
    int j = i - 9 * 2048;
    if (j >= 0 && j < 9 * 768) {        // offset conv
        int k  = j / 768;
        int r  = j % 768;
        int o  = r >> 5;
        int kp = r & 31;
        int c0 = 2 * kp;
        float v0 = (o < 18) ? ow[o * 576 + c0 * 9 + k] : 0.f;
        float v1 = (o < 18) ? ow[o * 576 + (c0 + 1) * 9 + k] : 0.f;
        float h0, l0, h1, l1;
        bfsplit(v0, h0, l0); bfsplit(v1, h1, l1);
        int word = swz_word36(o, kp);
        g_wboh[k * (24 * ROWW) + word] = bfpack(h0, h1);
        g_wbol[k * (24 * ROWW) + word] = bfpack(l0, l1);
    }
    int l = j - 9 * 768;
    if (l >= 0 && l < 9 * 512) {        // mod conv
        int k  = l / 512;
        int r  = l % 512;
        int o  = r >> 5;
        int kp = r & 31;
        int c0 = 2 * kp;
        float v0 = (o < 9) ? mw[o * 576 + c0 * 9 + k] : 0.f;
        float v1 = (o < 9) ? mw[o * 576 + (c0 + 1) * 9 + k] : 0.f;
        float h0, l0, h1, l1;
        bfsplit(v0, h0, l0); bfsplit(v1, h1, l1);
        int word = swz_word36(o, kp);
        g_wbmh[k * (16 * ROWW) + word] = bfpack(h0, h1);
        g_wbml[k * (16 * ROWW) + word] = bfpack(l0, l1);
    }
}

// ---------------------------------------------------------------------------
// Kernel 1: offset+mod convs as bf16 MMA GEMMs (R12 form, unchanged).
// ---------------------------------------------------------------------------
#define A_HI  0
#define A_LO  (A_HI + 128 * ROWW)
#define BO_HI (A_LO + 128 * ROWW)
#define BO_LO (BO_HI + 24 * ROWW)
#define BM_HI (BO_LO + 24 * ROWW)
#define BM_LO (BM_HI + 16 * ROWW)
#define OM_WORDS (BM_LO + 16 * ROWW)    // 12096 words = 48384 B

__global__ __launch_bounds__(128, 4)
void offmask_kernel(const float* __restrict__ omap, const float* __restrict__ mmap,
                    const float* __restrict__ obias, const float* __restrict__ mbias)
{
    extern __shared__ uint32_t smu[];

    const int tid  = threadIdx.x;
    const int lane = tid & 31;
    const int warp = tid >> 5;
    const int g    = lane >> 2;
    const int tg   = lane & 3;

    const int b    = blockIdx.x >> 7;
    const int row  = blockIdx.x & 127;
    const int pix  = tid;
    const int swzp = (pix >> 2) & 3;

    const float* ob = omap + (size_t)b * Cc * HW;
    const float* mb = mmap + (size_t)b * Cc * HW;

    float d1[2][3][4];
    float d2[2][2][4];
#pragma unroll
    for (int mt = 0; mt < 2; mt++) {
#pragma unroll
        for (int nt = 0; nt < 3; nt++)
#pragma unroll
            for (int r = 0; r < 4; r++) d1[mt][nt][r] = 0.f;
#pragma unroll
        for (int nt = 0; nt < 2; nt++)
#pragma unroll
            for (int r = 0; r < 4; r++) d2[mt][nt][r] = 0.f;
    }

#pragma unroll 1
    for (int k = 0; k < 9; k++) {
        const int ki = k / 3, kj = k % 3;
        const int py = row - 1 + ki;
        const int px = pix - 1 + kj;
        const bool valid = ((unsigned)py < (unsigned)Hh) & ((unsigned)px < (unsigned)Ww);

        // ---- PASS 1: offset conv ----
        __syncthreads();
        {
            const uint4* soh = (const uint4*)&g_wboh[k * (24 * ROWW)];
            const uint4* sol = (const uint4*)&g_wbol[k * (24 * ROWW)];
            const uint4* smh = (const uint4*)&g_wbmh[k * (16 * ROWW)];
            const uint4* sml = (const uint4*)&g_wbml[k * (16 * ROWW)];
#pragma unroll
            for (int i = tid; i < 216; i += 128) {
                ((uint4*)&smu[BO_HI])[i] = soh[i];
                ((uint4*)&smu[BO_LO])[i] = sol[i];
            }
#pragma unroll
            for (int i = tid; i < 144; i += 128) {
                ((uint4*)&smu[BM_HI])[i] = smh[i];
                ((uint4*)&smu[BM_LO])[i] = sml[i];
            }
        }
        {
            const float* qo = ob + py * Ww + px;
#pragma unroll
            for (int ks = 0; ks < 4; ks++) {
#pragma unroll
                for (int kp0 = 0; kp0 < 4; kp0++) {
                    const int cA = 16 * ks + 2 * kp0;
                    const int cs[4] = { cA, cA + 1, cA + 8, cA + 9 };
                    float so[4];
#pragma unroll
                    for (int j = 0; j < 4; j++)
                        so[j] = valid ? __ldg(qo + cs[j] * HW) : 0.f;
                    float h[4], l[4];
#pragma unroll
                    for (int j = 0; j < 4; j++) bfsplit(so[j], h[j], l[j]);
                    const int wbase = pix * ROWW + ks * 8 + 2 * (kp0 ^ swzp);
                    *(uint2*)&smu[A_HI + wbase] = make_uint2(bfpack(h[0], h[1]), bfpack(h[2], h[3]));
                    *(uint2*)&smu[A_LO + wbase] = make_uint2(bfpack(l[0], l[1]), bfpack(l[2], l[3]));
                }
            }
        }
        __syncthreads();
#pragma unroll
        for (int ks = 0; ks < 4; ks++) {
            uint32_t ah[2][4], al[2][4];
#pragma unroll
            for (int mt = 0; mt < 2; mt++) {
                const int r0 = warp * 32 + mt * 16 + g;
                const int r1 = r0 + 8;
                const int w0 = r0 * ROWW + ks * 8 + 2 * (tg ^ ((r0 >> 2) & 3));
                const int w1 = r1 * ROWW + ks * 8 + 2 * (tg ^ ((r1 >> 2) & 3));
                uint2 H0 = *(const uint2*)&smu[A_HI + w0];
                uint2 H1 = *(const uint2*)&smu[A_HI + w1];
                uint2 L0 = *(const uint2*)&smu[A_LO + w0];
                uint2 L1 = *(const uint2*)&smu[A_LO + w1];
                ah[mt][0] = H0.x; ah[mt][1] = H1.x; ah[mt][2] = H0.y; ah[mt][3] = H1.y;
                al[mt][0] = L0.x; al[mt][1] = L1.x; al[mt][2] = L0.y; al[mt][3] = L1.y;
            }
#pragma unroll
            for (int nt = 0; nt < 3; nt++) {
                const int o  = nt * 8 + g;
                const int wb = o * ROWW + ks * 8 + 2 * (tg ^ ((o >> 2) & 3));
                uint2 bh = *(const uint2*)&smu[BO_HI + wb];
                uint2 bl = *(const uint2*)&smu[BO_LO + wb];
#pragma unroll
                for (int mt = 0; mt < 2; mt++) {
                    MMA_BF16(d1[mt][nt], ah[mt], bh.x, bh.y);
                    MMA_BF16(d1[mt][nt], al[mt], bh.x, bh.y);
                    MMA_BF16(d1[mt][nt], ah[mt], bl.x, bl.y);
                }
            }
        }

        // ---- PASS 2: mod conv ----
        __syncthreads();
        {
            const float* qm = mb + py * Ww + px;
#pragma unroll
            for (int ks = 0; ks < 4; ks++) {
#pragma unroll
                for (int kp0 = 0; kp0 < 4; kp0++) {
                    const int cA = 16 * ks + 2 * kp0;
                    const int cs[4] = { cA, cA + 1, cA + 8, cA + 9 };
                    float sm[4];
#pragma unroll
                    for (int j = 0; j < 4; j++)
                        sm[j] = valid ? __ldg(qm + cs[j] * HW) : 0.f;
                    float h[4], l[4];
#pragma unroll
                    for (int j = 0; j < 4; j++) bfsplit(sm[j], h[j], l[j]);
                    const int wbase = pix * ROWW + ks * 8 + 2 * (kp0 ^ swzp);
                    *(uint2*)&smu[A_HI + wbase] = make_uint2(bfpack(h[0], h[1]), bfpack(h[2], h[3]));
                    *(uint2*)&smu[A_LO + wbase] = make_uint2(bfpack(l[0], l[1]), bfpack(l[2], l[3]));
                }
            }
        }
        __syncthreads();
#pragma unroll
        for (int ks = 0; ks < 4; ks++) {
            uint32_t ah[2][4], al[2][4];
#pragma unroll
            for (int mt = 0; mt < 2; mt++) {
                const int r0 = warp * 32 + mt * 16 + g;
                const int r1 = r0 + 8;
                const int w0 = r0 * ROWW + ks * 8 + 2 * (tg ^ ((r0 >> 2) & 3));
                const int w1 = r1 * ROWW + ks * 8 + 2 * (tg ^ ((r1 >> 2) & 3));
                uint2 H0 = *(const uint2*)&smu[A_HI + w0];
                uint2 H1 = *(const uint2*)&smu[A_HI + w1];
                uint2 L0 = *(const uint2*)&smu[A_LO + w0];
                uint2 L1 = *(const uint2*)&smu[A_LO + w1];
                ah[mt][0] = H0.x; ah[mt][1] = H1.x; ah[mt][2] = H0.y; ah[mt][3] = H1.y;
                al[mt][0] = L0.x; al[mt][1] = L1.x; al[mt][2] = L0.y; al[mt][3] = L1.y;
            }
#pragma unroll
            for (int nt = 0; nt < 2; nt++) {
                const int o  = nt * 8 + g;
                const int wb = o * ROWW + ks * 8 + 2 * (tg ^ ((o >> 2) & 3));
                uint2 bh = *(const uint2*)&smu[BM_HI + wb];
                uint2 bl = *(const uint2*)&smu[BM_LO + wb];
#pragma unroll
                for (int mt = 0; mt < 2; mt++) {
                    MMA_BF16(d2[mt][nt], ah[mt], bh.x, bh.y);
                    MMA_BF16(d2[mt][nt], al[mt], bh.x, bh.y);
                    MMA_BF16(d2[mt][nt], ah[mt], bl.x, bl.y);
                }
            }
        }
    }

    // ---- epilogue ----
    float* S = g_scratch + (size_t)b * 27 * HW + row * Ww;
#pragma unroll
    for (int mt = 0; mt < 2; mt++) {
        const int r0 = warp * 32 + mt * 16 + g;
        const int r1 = r0 + 8;
#pragma unroll
        for (int nt = 0; nt < 3; nt++) {
            const int t0 = nt * 8 + tg * 2;
#pragma unroll
            for (int e = 0; e < 2; e++) {
                const int t = t0 + e;
                if (t < 18) {
                    const int plane = (t & 1) ? (9 + (t >> 1)) : (t >> 1);
                    const float bias = __ldg(&obias[t]);
                    S[plane * HW + r0] = d1[mt][nt][e]     + bias;
                    S[plane * HW + r1] = d1[mt][nt][e + 2] + bias;
                }
            }
        }
#pragma unroll
        for (int nt = 0; nt < 2; nt++) {
            const int t0 = nt * 8 + tg * 2;
#pragma unroll
            for (int e = 0; e < 2; e++) {
                const int t = t0 + e;
                if (t < 9) {
                    const float bias = __ldg(&mbias[t]);
                    float z0 = d2[mt][nt][e]     + bias;
                    float z1 = d2[mt][nt][e + 2] + bias;
                    S[(18 + t) * HW + r0] = 2.0f / (1.0f + expf(-z0));
                    S[(18 + t) * HW + r1] = 2.0f / (1.0f + expf(-z1));
                }
            }
        }
    }
}

// ---------------------------------------------------------------------------
// Kernel 2: deformable conv bf16 MMA implicit GEMM, 2 IMAGE ROWS per CTA.
// M = 256 pixels, 256 threads (thread = pixel: row = row0 + (tid>>7),
// col = tid&127), 8 warps each owning 32 M-rows (2 m-tiles of 16).
// Per-pixel B-staging and barrier cost halved; 92 KB smem -> 2 CTAs/SM
// (16 warps/SM). Per-thread sample/MMA code identical to R11.
// ---------------------------------------------------------------------------
#define SA_HI 0
#define SA_LO (SA_HI + 256 * ROWW)        //  9216
#define SB_HI (SA_LO + 256 * ROWW)        // 18432 (64*36 = 2304)
#define SB_LO (SB_HI + 64 * ROWW)         // 20736
#define SM_WORDS (SB_LO + 64 * ROWW)      // 23040 words = 92160 B

__global__ __launch_bounds__(256, 2)
void deform_kernel(const float* __restrict__ x, float* __restrict__ out)
{
    extern __shared__ uint32_t smu[];

    const int tid  = threadIdx.x;
    const int lane = tid & 31;
    const int warp = tid >> 5;
    const int g    = lane >> 2;
    const int tg   = lane & 3;

    const int b    = blockIdx.x >> 6;          // 0..3
    const int row0 = (blockIdx.x & 63) * 2;    // first of 2 rows
    const int pix  = tid;                      // M-row index 0..255
    const int row  = row0 + (pix >> 7);
    const int col  = pix & 127;
    const int p    = row * Ww + col;
    const int swzp = (pix >> 2) & 3;

    const float* S  = g_scratch + (size_t)b * 27 * HW;
    const float* xb = x + (size_t)b * Cc * HW;

    float acc[2][8][4];
#pragma unroll
    for (int mt = 0; mt < 2; mt++)
#pragma unroll
        for (int nt = 0; nt < 8; nt++)
#pragma unroll
            for (int r = 0; r < 4; r++) acc[mt][nt][r] = 0.f;

#pragma unroll 1
    for (int k = 0; k < 9; k++) {
        __syncthreads();   // previous tap's fragment reads complete

        // ---- stage B tiles (576 uint4 over 256 threads) ----
        {
            const uint4* sh = (const uint4*)&g_wbh[k * (64 * ROWW)];
            const uint4* sl = (const uint4*)&g_wbl[k * (64 * ROWW)];
            uint4* dh = (uint4*)&smu[SB_HI];
            uint4* dl = (uint4*)&smu[SB_LO];
#pragma unroll
            for (int i = tid; i < 576; i += 256) {
                dh[i] = sh[i];
                dl[i] = sl[i];
            }
        }

        // ---- tap descriptor ----
        const float dy = S[k * HW + p];
        const float dx = S[(9 + k) * HW + p];
        const float m  = S[(18 + k) * HW + p];
        const float py = dy + (float)(row - 1 + k / 3);
        const float px = dx + (float)(col - 1 + k % 3);
        const float fy = floorf(py), fx = floorf(px);
        const int y0 = (int)fy, x0 = (int)fx;
        const int y1 = y0 + 1,  x1 = x0 + 1;
        const float wy = py - fy, wx = px - fx;

        const bool vy0 = ((unsigned)y0 < (unsigned)Hh);
        const bool vy1 = ((unsigned)y1 < (unsigned)Hh);
        const bool vx0 = ((unsigned)x0 < (unsigned)Ww);
        const bool vx1 = ((unsigned)x1 < (unsigned)Ww);
        const int y0c = min(max(y0, 0), Hh - 1);
        const int y1c = min(max(y1, 0), Hh - 1);
        const int x0c = min(max(x0, 0), Ww - 1);
        const int x1c = min(max(x1, 0), Ww - 1);

        float c00 = (1.f - wy) * (1.f - wx) * m; c00 = (vy0 & vx0) ? c00 : 0.f;
        float c01 = (1.f - wy) * wx         * m; c01 = (vy0 & vx1) ? c01 : 0.f;
        float c10 = wy * (1.f - wx)         * m; c10 = (vy1 & vx0) ? c10 : 0.f;
        float c11 = wy * wx                 * m; c11 = (vy1 & vx1) ? c11 : 0.f;

        const float* q00 = xb + y0c * Ww + x0c;
        const float* q01 = xb + y0c * Ww + x1c;
        const float* q10 = xb + y1c * Ww + x0c;
        const float* q11 = xb + y1c * Ww + x1c;

        // ---- sample 64 channels, split hi/lo, STS into A tiles ----
#pragma unroll
        for (int ks = 0; ks < 4; ks++) {
#pragma unroll
            for (int kp0 = 0; kp0 < 4; kp0++) {
                const int cA = 16 * ks + 2 * kp0;
                const int cs[4] = { cA, cA + 1, cA + 8, cA + 9 };
                float s[4];
#pragma unroll
                for (int j = 0; j < 4; j++) {
                    const int c = cs[j];
                    float v = __ldg(q00 + c * HW) * c00;
                    v = fmaf(__ldg(q01 + c * HW), c01, v);
                    v = fmaf(__ldg(q10 + c * HW), c10, v);
                    v = fmaf(__ldg(q11 + c * HW), c11, v);
                    s[j] = v;
                }
                float h0, l0, h1, l1, h2, l2, h3, l3;
                bfsplit(s[0], h0, l0); bfsplit(s[1], h1, l1);
                bfsplit(s[2], h2, l2); bfsplit(s[3], h3, l3);
                const int wbase = pix * ROWW + ks * 8 + 2 * (kp0 ^ swzp);
                *(uint2*)&smu[SA_HI + wbase] = make_uint2(bfpack(h0, h1), bfpack(h2, h3));
                *(uint2*)&smu[SA_LO + wbase] = make_uint2(bfpack(l0, l1), bfpack(l2, l3));
            }
        }

        __syncthreads();

        // ---- GEMM: 4 k-steps x (2 m-tiles x 8 n-tiles) x 3 products ----
#pragma unroll
        for (int ks = 0; ks < 4; ks++) {
            uint32_t ah[2][4], al[2][4];
#pragma unroll
            for (int mt = 0; mt < 2; mt++) {
                const int r0 = warp * 32 + mt * 16 + g;
                const int r1 = r0 + 8;
                const int w0 = r0 * ROWW + ks * 8 + 2 * (tg ^ ((r0 >> 2) & 3));
                const int w1 = r1 * ROWW + ks * 8 + 2 * (tg ^ ((r1 >> 2) & 3));
                uint2 H0 = *(const uint2*)&smu[SA_HI + w0];
                uint2 H1 = *(const uint2*)&smu[SA_HI + w1];
                uint2 L0 = *(const uint2*)&smu[SA_LO + w0];
                uint2 L1 = *(const uint2*)&smu[SA_LO + w1];
                ah[mt][0] = H0.x; ah[mt][1] = H1.x; ah[mt][2] = H0.y; ah[mt][3] = H1.y;
                al[mt][0] = L0.x; al[mt][1] = L1.x; al[mt][2] = L0.y; al[mt][3] = L1.y;
            }
#pragma unroll
            for (int nt = 0; nt < 8; nt++) {
                const int o  = nt * 8 + g;
                const int wb = o * ROWW + ks * 8 + 2 * (tg ^ ((o >> 2) & 3));
                uint2 bh = *(const uint2*)&smu[SB_HI + wb];
                uint2 bl = *(const uint2*)&smu[SB_LO + wb];
#pragma unroll
                for (int mt = 0; mt < 2; mt++) {
                    MMA_BF16(acc[mt][nt], ah[mt], bh.x, bh.y);
                    MMA_BF16(acc[mt][nt], al[mt], bh.x, bh.y);
                    MMA_BF16(acc[mt][nt], ah[mt], bl.x, bl.y);
                }
            }
        }
    }

    // ---- epilogue: tile row r -> image (row0 + (r>>7), r&127) ----
    float* ob = out + (size_t)b * Oo * HW;
#pragma unroll
    for (int mt = 0; mt < 2; mt++) {
        const int r0 = warp * 32 + mt * 16 + g;
        const int r1 = r0 + 8;
        const int p0 = (row0 + (r0 >> 7)) * Ww + (r0 & 127);
        const int p1 = (row0 + (r1 >> 7)) * Ww + (r1 & 127);
#pragma unroll
        for (int nt = 0; nt < 8; nt++) {
            const int o0 = nt * 8 + tg * 2;
            ob[(o0)     * HW + p0] = acc[mt][nt][0];
            ob[(o0 + 1) * HW + p0] = acc[mt][nt][1];
            ob[(o0)     * HW + p1] = acc[mt][nt][2];
            ob[(o0 + 1) * HW + p1] = acc[mt][nt][3];
        }
    }
}

// ---------------------------------------------------------------------------

extern "C" void kernel_launch(void* const* d_in, const int* in_sizes, int n_in,
                              void* d_out, int out_size)
{
    const float* x     = (const float*)d_in[0];
    const float* omap  = (const float*)d_in[1];
    const float* mmap  = (const float*)d_in[2];
    const float* ow    = (const float*)d_in[3];
    const float* obias = (const float*)d_in[4];
    const float* mw    = (const float*)d_in[5];
    const float* mbias = (const float*)d_in[6];
    const float* w     = (const float*)d_in[7];
    float* out = (float*)d_out;

    const int prep_total = 9 * 2048 + 9 * 768 + 9 * 512;   // 29952
    prep_kernel<<<(prep_total + 255) / 256, 256>>>(w, ow, mw);

    const int om_smem = OM_WORDS * (int)sizeof(uint32_t);  // 48384
    cudaFuncSetAttribute(offmask_kernel, cudaFuncAttributeMaxDynamicSharedMemorySize, om_smem);
    offmask_kernel<<<Bb * Hh, 128, om_smem>>>(omap, mmap, obias, mbias);

    const int df_smem = SM_WORDS * (int)sizeof(uint32_t);  // 92160
    cudaFuncSetAttribute(deform_kernel, cudaFuncAttributeMaxDynamicSharedMemorySize, df_smem);
    deform_kernel<<<Bb * (Hh / 2), 256, df_smem>>>(x, out);
}